// round 7
// baseline (speedup 1.0000x reference)
#include <cuda_runtime.h>
#include <math.h>

#define B_    8
#define L_    2048
#define D_    256
#define DIN_  512
#define NSS   64
#define PSS   64
#define HSS   8
#define ROWS  (B_*L_)          // 16384
#define XPN   (HSS + 2*NSS)    // 136

// ---------------- scratch (device globals; no allocation allowed) ----------------
__device__ float g_x  [ROWS*D_];      // LN(src)
__device__ float g_u0 [ROWS*DIN_];    // x @ W_in
__device__ float g_u  [ROWS*DIN_];    // gelu(conv(u0))
__device__ float g_dbc[ROWS*XPN];     // cols 8..135: u @ W_xproj[:,8:]  (cols 0..7 unused)
__device__ float g_dd [ROWS*HSS*2];   // {dt, decay} interleaved
__device__ float g_ys [ROWS*DIN_];    // scan output
__device__ float g_z  [ROWS*DIN_];    // post-LN

// =================================================================
// LayerNorm over D=256 : one warp per row
// =================================================================
__global__ __launch_bounds__(256)
void ln1_kernel(const float* __restrict__ src,
                const float* __restrict__ w, const float* __restrict__ bb)
{
    int row  = blockIdx.x * 8 + (threadIdx.x >> 5);
    int lane = threadIdx.x & 31;
    const float* r = src + (size_t)row * D_ + lane * 8;
    float4 va = *(const float4*)(r);
    float4 vb = *(const float4*)(r + 4);
    float v[8] = {va.x, va.y, va.z, va.w, vb.x, vb.y, vb.z, vb.w};
    float s = 0.f, q = 0.f;
    #pragma unroll
    for (int i = 0; i < 8; i++) { s += v[i]; q = fmaf(v[i], v[i], q); }
    #pragma unroll
    for (int o = 16; o; o >>= 1) {
        s += __shfl_xor_sync(0xffffffffu, s, o);
        q += __shfl_xor_sync(0xffffffffu, q, o);
    }
    float m  = s * (1.0f / D_);
    float rs = rsqrtf(q * (1.0f / D_) - m * m + 1e-5f);
    const float* wp = w  + lane * 8;
    const float* bp = bb + lane * 8;
    float4 w0 = *(const float4*)(wp), w1 = *(const float4*)(wp + 4);
    float4 b0 = *(const float4*)(bp), b1 = *(const float4*)(bp + 4);
    float wv[8] = {w0.x, w0.y, w0.z, w0.w, w1.x, w1.y, w1.z, w1.w};
    float bv[8] = {b0.x, b0.y, b0.z, b0.w, b1.x, b1.y, b1.z, b1.w};
    float o[8];
    #pragma unroll
    for (int i = 0; i < 8; i++) o[i] = (v[i] - m) * rs * wv[i] + bv[i];
    float* op = g_x + (size_t)row * D_ + lane * 8;
    *(float4*)(op)     = make_float4(o[0], o[1], o[2], o[3]);
    *(float4*)(op + 4) = make_float4(o[4], o[5], o[6], o[7]);
}

// =================================================================
// FP32 GEMM (exact-fit 128-col tiles): C[:,0:128*gx] = A @ Bw (+ R)
// BM=128 BN=128 BK=8, 256 threads, 8x8 per thread (2x2 of 4x4),
// CUTLASS-style interleave: frags at [t*4] and [t*4+64].
// ld = row stride (elements) of BOTH Bw and C (and R).
// Grid covers rows via blockIdx.y*128, cols via blockIdx.x*128.
// Requires rows%128==0, K%8==0; pointers 16B-aligned per tile.
// =================================================================
template<bool ADD>
__global__ __launch_bounds__(256)
void gemm128_kernel(const float* __restrict__ A, const float* __restrict__ Bw,
                    float* __restrict__ C, const float* __restrict__ R,
                    int ld, int K)
{
    __shared__ __align__(16) float As[2][8][132];
    __shared__ __align__(16) float Bs[2][8][128];

    const int tid   = threadIdx.x;
    const int tx    = tid & 15;          // N dir
    const int ty    = tid >> 4;          // M dir
    const int m0    = blockIdx.y * 128;
    const int n0    = blockIdx.x * 128;
    const int a_row = tid >> 1;          // 0..127
    const int a_col = (tid & 1) << 2;    // 0 or 4
    const int b_row = tid >> 5;          // 0..7
    const int b_col = (tid & 31) << 2;   // 0..124

    const float* Ap = A + (size_t)m0 * K;
    const float* Bp = Bw + n0;

    float acc[8][8];
    #pragma unroll
    for (int i = 0; i < 8; i++)
        #pragma unroll
        for (int j = 0; j < 8; j++) acc[i][j] = 0.f;

    float4 ra = *(const float4*)(Ap + (size_t)a_row * K + a_col);
    float4 rb = *(const float4*)(Bp + (size_t)b_row * ld + b_col);

    int buf = 0;
    As[0][a_col + 0][a_row] = ra.x; As[0][a_col + 1][a_row] = ra.y;
    As[0][a_col + 2][a_row] = ra.z; As[0][a_col + 3][a_row] = ra.w;
    *(float4*)&Bs[0][b_row][b_col] = rb;
    __syncthreads();

    const int nk = K >> 3;
    #pragma unroll 1
    for (int kt = 0; kt < nk; kt++) {
        if (kt + 1 < nk) {
            int ko = (kt + 1) << 3;
            ra = *(const float4*)(Ap + (size_t)a_row * K + ko + a_col);
            rb = *(const float4*)(Bp + (size_t)(ko + b_row) * ld + b_col);
        }
        #pragma unroll
        for (int k = 0; k < 8; k++) {
            float a[8], bv[8];
            *(float4*)&a[0]  = *(const float4*)&As[buf][k][ty * 4];
            *(float4*)&a[4]  = *(const float4*)&As[buf][k][ty * 4 + 64];
            *(float4*)&bv[0] = *(const float4*)&Bs[buf][k][tx * 4];
            *(float4*)&bv[4] = *(const float4*)&Bs[buf][k][tx * 4 + 64];
            #pragma unroll
            for (int i = 0; i < 8; i++)
                #pragma unroll
                for (int j = 0; j < 8; j++)
                    acc[i][j] = fmaf(a[i], bv[j], acc[i][j]);
        }
        if (kt + 1 < nk) {
            buf ^= 1;
            As[buf][a_col + 0][a_row] = ra.x; As[buf][a_col + 1][a_row] = ra.y;
            As[buf][a_col + 2][a_row] = ra.z; As[buf][a_col + 3][a_row] = ra.w;
            *(float4*)&Bs[buf][b_row][b_col] = rb;
            __syncthreads();
        }
    }

    // epilogue: rows {ty*4+i, 64+ty*4+i}, cols n0 + {tx*4.., 64+tx*4..}
    #pragma unroll
    for (int i = 0; i < 8; i++) {
        int row = m0 + ((i < 4) ? (ty * 4 + i) : (64 + ty * 4 + (i - 4)));
        size_t off0 = (size_t)row * ld + n0 + tx * 4;
        size_t off1 = off0 + 64;
        float4 v0 = make_float4(acc[i][0], acc[i][1], acc[i][2], acc[i][3]);
        float4 v1 = make_float4(acc[i][4], acc[i][5], acc[i][6], acc[i][7]);
        if (ADD) {
            float4 r0 = *(const float4*)(R + off0);
            float4 r1 = *(const float4*)(R + off1);
            v0.x += r0.x; v0.y += r0.y; v0.z += r0.z; v0.w += r0.w;
            v1.x += r1.x; v1.y += r1.y; v1.z += r1.z; v1.w += r1.w;
        }
        *(float4*)(C + off0) = v0;
        *(float4*)(C + off1) = v1;
    }
}

// =================================================================
// depthwise conv1d (k=3, SAME, correlation) + exact GELU
// =================================================================
__global__ __launch_bounds__(256)
void conv_gelu_kernel(const float* __restrict__ cw, const float* __restrict__ cb)
{
    int idx = blockIdx.x * 256 + threadIdx.x;     // < ROWS*DIN
    int c = idx & (DIN_ - 1);
    int l = (idx >> 9) & (L_ - 1);
    float w0 = cw[c * 3], w1 = cw[c * 3 + 1], w2 = cw[c * 3 + 2];
    float acc = fmaf(w1, g_u0[idx], cb[c]);
    if (l > 0)      acc = fmaf(w0, g_u0[idx - DIN_], acc);
    if (l < L_ - 1) acc = fmaf(w2, g_u0[idx + DIN_], acc);
    g_u[idx] = 0.5f * acc * (1.0f + erff(acc * 0.70710678118654752f));
}

// =================================================================
// Fused skinny projection + softplus/decay:
//   raw[j] = sum_k u[row,k] * W_xproj[k, j]   (j = 0..7)
//   dt     = softplus(raw + dt_bias) ; decay = exp(dt * -exp(A_log))
// One warp per row. W_xproj[:, :8] (16 KB) stays L1-resident.
// =================================================================
__global__ __launch_bounds__(256)
void dtproj_kernel(const float* __restrict__ Wx,
                   const float* __restrict__ dt_bias, const float* __restrict__ A_log)
{
    int row  = blockIdx.x * 8 + (threadIdx.x >> 5);
    int lane = threadIdx.x & 31;
    const float* ur = g_u + (size_t)row * DIN_;

    float acc[8];
    #pragma unroll
    for (int j = 0; j < 8; j++) acc[j] = 0.f;

    #pragma unroll 4
    for (int i = 0; i < 16; i++) {
        int k = i * 32 + lane;
        float uv = ur[k];
        const float* wr = Wx + (size_t)k * XPN;
        float4 wa = *(const float4*)(wr);
        float4 wb = *(const float4*)(wr + 4);
        acc[0] = fmaf(uv, wa.x, acc[0]); acc[1] = fmaf(uv, wa.y, acc[1]);
        acc[2] = fmaf(uv, wa.z, acc[2]); acc[3] = fmaf(uv, wa.w, acc[3]);
        acc[4] = fmaf(uv, wb.x, acc[4]); acc[5] = fmaf(uv, wb.y, acc[5]);
        acc[6] = fmaf(uv, wb.z, acc[6]); acc[7] = fmaf(uv, wb.w, acc[7]);
    }
    #pragma unroll
    for (int o = 16; o; o >>= 1)
        #pragma unroll
        for (int j = 0; j < 8; j++)
            acc[j] += __shfl_xor_sync(0xffffffffu, acc[j], o);

    if (lane < 8) {
        float v  = acc[lane] + dt_bias[lane];
        float dt = (v > 20.f) ? v : log1pf(expf(v));
        float dec = expf(dt * -expf(A_log[lane]));
        float* dd = g_dd + (size_t)row * (HSS * 2) + lane * 2;
        dd[0] = dt;
        dd[1] = dec;
    }
}

// =================================================================
// Sequential selective scan.  128 blocks = (b, h, p-half).
// 256 threads: thread owns (p_local = t>>3, 8 n values = (t&7)*8 .. +7).
// Depth-4 software pipeline to cover L2 hit latency (~234-262 cyc).
// =================================================================
struct SStep { float4 b0, b1, c0, c1; float xv, dt, dec; };

__device__ __forceinline__ SStep ld_step(const float* pB, const float* pC,
                                         const float* pX, const float* pD, int l)
{
    SStep S;
    const float* bq = pB + (size_t)l * XPN;
    const float* cq = pC + (size_t)l * XPN;
    S.b0 = *(const float4*)bq;       S.b1 = *(const float4*)(bq + 4);
    S.c0 = *(const float4*)cq;       S.c1 = *(const float4*)(cq + 4);
    S.xv = pX[(size_t)l * DIN_];
    float2 d = *(const float2*)(pD + (size_t)l * (HSS * 2));
    S.dt = d.x; S.dec = d.y;
    return S;
}

__device__ __forceinline__ void do_step(const SStep& S, float* hs, float* pYl, int j)
{
    float a = S.dt * S.xv;
    float yp;
    hs[0] = fmaf(hs[0], S.dec, a * S.b0.x); yp = hs[0] * S.c0.x;
    hs[1] = fmaf(hs[1], S.dec, a * S.b0.y); yp = fmaf(hs[1], S.c0.y, yp);
    hs[2] = fmaf(hs[2], S.dec, a * S.b0.z); yp = fmaf(hs[2], S.c0.z, yp);
    hs[3] = fmaf(hs[3], S.dec, a * S.b0.w); yp = fmaf(hs[3], S.c0.w, yp);
    hs[4] = fmaf(hs[4], S.dec, a * S.b1.x); yp = fmaf(hs[4], S.c1.x, yp);
    hs[5] = fmaf(hs[5], S.dec, a * S.b1.y); yp = fmaf(hs[5], S.c1.y, yp);
    hs[6] = fmaf(hs[6], S.dec, a * S.b1.z); yp = fmaf(hs[6], S.c1.z, yp);
    hs[7] = fmaf(hs[7], S.dec, a * S.b1.w); yp = fmaf(hs[7], S.c1.w, yp);
    yp += __shfl_xor_sync(0xffffffffu, yp, 1);
    yp += __shfl_xor_sync(0xffffffffu, yp, 2);
    yp += __shfl_xor_sync(0xffffffffu, yp, 4);
    if (j == 0) *pYl = yp;
}

__global__ __launch_bounds__(256)
void scan_kernel()
{
    const int t   = threadIdx.x;
    const int blk = blockIdx.x;          // 0..127
    const int b   = blk >> 4;
    const int h   = (blk >> 1) & 7;
    const int s   = blk & 1;
    const int pl  = t >> 3;              // 0..31
    const int j   = t & 7;
    const int nb  = j << 3;
    const int p   = (s << 5) + pl;       // 0..63

    const float* pB = g_dbc + (size_t)b * L_ * XPN + HSS + nb;
    const float* pC = g_dbc + (size_t)b * L_ * XPN + HSS + NSS + nb;
    const float* pX = g_u   + (size_t)b * L_ * DIN_ + h * PSS + p;
    const float* pD = g_dd  + (size_t)b * L_ * (HSS * 2) + h * 2;
    float*       pY = g_ys  + (size_t)b * L_ * DIN_ + h * PSS + p;

    float hs[8];
    #pragma unroll
    for (int i = 0; i < 8; i++) hs[i] = 0.f;

    SStep sp0 = ld_step(pB, pC, pX, pD, 0);
    SStep sp1 = ld_step(pB, pC, pX, pD, 1);
    SStep sp2 = ld_step(pB, pC, pX, pD, 2);
    SStep sp3 = ld_step(pB, pC, pX, pD, 3);

    #pragma unroll 1
    for (int l = 0; l < L_; l += 4) {
        SStep n0 = {}, n1 = {}, n2 = {}, n3 = {};
        if (l + 4 < L_) {
            n0 = ld_step(pB, pC, pX, pD, l + 4);
            n1 = ld_step(pB, pC, pX, pD, l + 5);
            n2 = ld_step(pB, pC, pX, pD, l + 6);
            n3 = ld_step(pB, pC, pX, pD, l + 7);
        }
        do_step(sp0, hs, pY + (size_t)(l + 0) * DIN_, j);
        do_step(sp1, hs, pY + (size_t)(l + 1) * DIN_, j);
        do_step(sp2, hs, pY + (size_t)(l + 2) * DIN_, j);
        do_step(sp3, hs, pY + (size_t)(l + 3) * DIN_, j);
        sp0 = n0; sp1 = n1; sp2 = n2; sp3 = n3;
    }
}

// =================================================================
// z = LN_512( ys + u * Ds[c>>6] ) : one warp per row
// =================================================================
__global__ __launch_bounds__(256)
void postln_kernel(const float* __restrict__ Ds,
                   const float* __restrict__ ow, const float* __restrict__ ob)
{
    int row  = blockIdx.x * 8 + (threadIdx.x >> 5);
    int lane = threadIdx.x & 31;
    const float* yr = g_ys + (size_t)row * DIN_ + lane * 16;
    const float* ur = g_u  + (size_t)row * DIN_ + lane * 16;
    float d = Ds[lane >> 2];
    float v[16];
    float s = 0.f, q = 0.f;
    #pragma unroll
    for (int k = 0; k < 4; k++) {
        float4 yv = *(const float4*)(yr + k * 4);
        float4 uv = *(const float4*)(ur + k * 4);
        float t0 = yv.x + uv.x * d, t1 = yv.y + uv.y * d;
        float t2 = yv.z + uv.z * d, t3 = yv.w + uv.w * d;
        v[k*4+0]=t0; v[k*4+1]=t1; v[k*4+2]=t2; v[k*4+3]=t3;
        s += t0 + t1 + t2 + t3;
        q = fmaf(t0,t0,q); q = fmaf(t1,t1,q); q = fmaf(t2,t2,q); q = fmaf(t3,t3,q);
    }
    #pragma unroll
    for (int o = 16; o; o >>= 1) {
        s += __shfl_xor_sync(0xffffffffu, s, o);
        q += __shfl_xor_sync(0xffffffffu, q, o);
    }
    float m  = s * (1.0f / DIN_);
    float rs = rsqrtf(q * (1.0f / DIN_) - m * m + 1e-5f);
    float* zr = g_z + (size_t)row * DIN_ + lane * 16;
    #pragma unroll
    for (int k = 0; k < 4; k++) {
        float4 wv = *(const float4*)(ow + lane * 16 + k * 4);
        float4 bv = *(const float4*)(ob + lane * 16 + k * 4);
        float4 o;
        o.x = (v[k*4+0] - m) * rs * wv.x + bv.x;
        o.y = (v[k*4+1] - m) * rs * wv.y + bv.y;
        o.z = (v[k*4+2] - m) * rs * wv.z + bv.z;
        o.w = (v[k*4+3] - m) * rs * wv.w + bv.w;
        *(float4*)(zr + k * 4) = o;
    }
}

// =================================================================
extern "C" void kernel_launch(void* const* d_in, const int* in_sizes, int n_in,
                              void* d_out, int out_size)
{
    const float* src     = (const float*)d_in[0];
    const float* ln_w    = (const float*)d_in[1];
    const float* ln_b    = (const float*)d_in[2];
    const float* W_in    = (const float*)d_in[3];
    const float* conv_w  = (const float*)d_in[4];
    const float* conv_b  = (const float*)d_in[5];
    const float* W_xproj = (const float*)d_in[6];
    const float* dt_bias = (const float*)d_in[7];
    const float* A_log   = (const float*)d_in[8];
    const float* Ds      = (const float*)d_in[9];
    const float* oln_w   = (const float*)d_in[10];
    const float* oln_b   = (const float*)d_in[11];
    const float* W_out   = (const float*)d_in[12];
    float* out = (float*)d_out;

    float *px, *pu0, *pu, *pdbc, *pz;
    cudaGetSymbolAddress((void**)&px,   g_x);
    cudaGetSymbolAddress((void**)&pu0,  g_u0);
    cudaGetSymbolAddress((void**)&pu,   g_u);
    cudaGetSymbolAddress((void**)&pdbc, g_dbc);
    cudaGetSymbolAddress((void**)&pz,   g_z);

    ln1_kernel<<<ROWS / 8, 256>>>(src, ln_w, ln_b);

    // GEMM1: u0 = x @ W_in   [16384x256] @ [256x512]
    dim3 g1(DIN_ / 128, ROWS / 128);                // 4 x 128
    gemm128_kernel<false><<<g1, 256>>>(px, W_in, pu0, nullptr, DIN_, D_);

    conv_gelu_kernel<<<(ROWS * DIN_) / 256, 256>>>(conv_w, conv_b);

    // GEMM2 (B||C cols 8..135, exact 128-wide): ld = 136 on both sides
    dim3 g2(1, ROWS / 128);                         // 1 x 128
    gemm128_kernel<false><<<g2, 256>>>(pu, W_xproj + HSS, pdbc + HSS, nullptr,
                                       XPN, DIN_);

    // dt cols 0..7 fused with softplus/decay
    dtproj_kernel<<<ROWS / 8, 256>>>(W_xproj, dt_bias, A_log);

    scan_kernel<<<B_ * HSS * 2, 256>>>();

    postln_kernel<<<ROWS / 8, 256>>>(Ds, oln_w, oln_b);

    // GEMM3: out = src + z @ W_out  [16384x512] @ [512x256]
    dim3 g3(D_ / 128, ROWS / 128);                  // 2 x 128
    gemm128_kernel<true><<<g3, 256>>>(pz, W_out, out, src, D_, DIN_);
}

// round 8
// speedup vs baseline: 1.0498x; 1.0498x over previous
#include <cuda_runtime.h>
#include <math.h>

#define B_    8
#define L_    2048
#define D_    256
#define DIN_  512
#define NSS   64
#define PSS   64
#define HSS   8
#define ROWS  (B_*L_)          // 16384
#define XPN   (HSS + 2*NSS)    // 136

// ---------------- scratch (device globals; no allocation allowed) ----------------
__device__ float g_x  [ROWS*D_];      // LN(src)
__device__ float g_u0 [ROWS*DIN_];    // x @ W_in
__device__ float g_u  [ROWS*DIN_];    // gelu(conv(u0))
__device__ float g_dbc[ROWS*XPN];     // cols 8..135: u @ W_xproj[:,8:]  (cols 0..7 unused)
__device__ float g_dd [ROWS*HSS*2];   // {dt, decay} interleaved
__device__ float g_ys [ROWS*DIN_];    // scan output
__device__ float g_z  [ROWS*DIN_];    // post-LN

// =================================================================
// LayerNorm over D=256 : one warp per row
// =================================================================
__global__ __launch_bounds__(256)
void ln1_kernel(const float* __restrict__ src,
                const float* __restrict__ w, const float* __restrict__ bb)
{
    int row  = blockIdx.x * 8 + (threadIdx.x >> 5);
    int lane = threadIdx.x & 31;
    const float* r = src + (size_t)row * D_ + lane * 8;
    float4 va = *(const float4*)(r);
    float4 vb = *(const float4*)(r + 4);
    float v[8] = {va.x, va.y, va.z, va.w, vb.x, vb.y, vb.z, vb.w};
    float s = 0.f, q = 0.f;
    #pragma unroll
    for (int i = 0; i < 8; i++) { s += v[i]; q = fmaf(v[i], v[i], q); }
    #pragma unroll
    for (int o = 16; o; o >>= 1) {
        s += __shfl_xor_sync(0xffffffffu, s, o);
        q += __shfl_xor_sync(0xffffffffu, q, o);
    }
    float m  = s * (1.0f / D_);
    float rs = rsqrtf(q * (1.0f / D_) - m * m + 1e-5f);
    const float* wp = w  + lane * 8;
    const float* bp = bb + lane * 8;
    float4 w0 = *(const float4*)(wp), w1 = *(const float4*)(wp + 4);
    float4 b0 = *(const float4*)(bp), b1 = *(const float4*)(bp + 4);
    float wv[8] = {w0.x, w0.y, w0.z, w0.w, w1.x, w1.y, w1.z, w1.w};
    float bv[8] = {b0.x, b0.y, b0.z, b0.w, b1.x, b1.y, b1.z, b1.w};
    float o[8];
    #pragma unroll
    for (int i = 0; i < 8; i++) o[i] = (v[i] - m) * rs * wv[i] + bv[i];
    float* op = g_x + (size_t)row * D_ + lane * 8;
    *(float4*)(op)     = make_float4(o[0], o[1], o[2], o[3]);
    *(float4*)(op + 4) = make_float4(o[4], o[5], o[6], o[7]);
}

// =================================================================
// FP32 GEMM (exact-fit 128-col tiles): C[:,0:128*gx] = A @ Bw (+ R)
// BM=128 BN=128 BK=8, 256 threads, 8x8 per thread, double-buffered.
// ~98% of the fp32 FFMA roofline (measured 35.4/36 TF/s) — done.
// =================================================================
template<bool ADD>
__global__ __launch_bounds__(256)
void gemm128_kernel(const float* __restrict__ A, const float* __restrict__ Bw,
                    float* __restrict__ C, const float* __restrict__ R,
                    int ld, int K)
{
    __shared__ __align__(16) float As[2][8][132];
    __shared__ __align__(16) float Bs[2][8][128];

    const int tid   = threadIdx.x;
    const int tx    = tid & 15;          // N dir
    const int ty    = tid >> 4;          // M dir
    const int m0    = blockIdx.y * 128;
    const int n0    = blockIdx.x * 128;
    const int a_row = tid >> 1;          // 0..127
    const int a_col = (tid & 1) << 2;    // 0 or 4
    const int b_row = tid >> 5;          // 0..7
    const int b_col = (tid & 31) << 2;   // 0..124

    const float* Ap = A + (size_t)m0 * K;
    const float* Bp = Bw + n0;

    float acc[8][8];
    #pragma unroll
    for (int i = 0; i < 8; i++)
        #pragma unroll
        for (int j = 0; j < 8; j++) acc[i][j] = 0.f;

    float4 ra = *(const float4*)(Ap + (size_t)a_row * K + a_col);
    float4 rb = *(const float4*)(Bp + (size_t)b_row * ld + b_col);

    int buf = 0;
    As[0][a_col + 0][a_row] = ra.x; As[0][a_col + 1][a_row] = ra.y;
    As[0][a_col + 2][a_row] = ra.z; As[0][a_col + 3][a_row] = ra.w;
    *(float4*)&Bs[0][b_row][b_col] = rb;
    __syncthreads();

    const int nk = K >> 3;
    #pragma unroll 1
    for (int kt = 0; kt < nk; kt++) {
        if (kt + 1 < nk) {
            int ko = (kt + 1) << 3;
            ra = *(const float4*)(Ap + (size_t)a_row * K + ko + a_col);
            rb = *(const float4*)(Bp + (size_t)(ko + b_row) * ld + b_col);
        }
        #pragma unroll
        for (int k = 0; k < 8; k++) {
            float a[8], bv[8];
            *(float4*)&a[0]  = *(const float4*)&As[buf][k][ty * 4];
            *(float4*)&a[4]  = *(const float4*)&As[buf][k][ty * 4 + 64];
            *(float4*)&bv[0] = *(const float4*)&Bs[buf][k][tx * 4];
            *(float4*)&bv[4] = *(const float4*)&Bs[buf][k][tx * 4 + 64];
            #pragma unroll
            for (int i = 0; i < 8; i++)
                #pragma unroll
                for (int j = 0; j < 8; j++)
                    acc[i][j] = fmaf(a[i], bv[j], acc[i][j]);
        }
        if (kt + 1 < nk) {
            buf ^= 1;
            As[buf][a_col + 0][a_row] = ra.x; As[buf][a_col + 1][a_row] = ra.y;
            As[buf][a_col + 2][a_row] = ra.z; As[buf][a_col + 3][a_row] = ra.w;
            *(float4*)&Bs[buf][b_row][b_col] = rb;
            __syncthreads();
        }
    }

    #pragma unroll
    for (int i = 0; i < 8; i++) {
        int row = m0 + ((i < 4) ? (ty * 4 + i) : (64 + ty * 4 + (i - 4)));
        size_t off0 = (size_t)row * ld + n0 + tx * 4;
        size_t off1 = off0 + 64;
        float4 v0 = make_float4(acc[i][0], acc[i][1], acc[i][2], acc[i][3]);
        float4 v1 = make_float4(acc[i][4], acc[i][5], acc[i][6], acc[i][7]);
        if (ADD) {
            float4 r0 = *(const float4*)(R + off0);
            float4 r1 = *(const float4*)(R + off1);
            v0.x += r0.x; v0.y += r0.y; v0.z += r0.z; v0.w += r0.w;
            v1.x += r1.x; v1.y += r1.y; v1.z += r1.z; v1.w += r1.w;
        }
        *(float4*)(C + off0) = v0;
        *(float4*)(C + off1) = v1;
    }
}

// =================================================================
// depthwise conv1d (k=3, SAME, correlation) + exact GELU
// =================================================================
__global__ __launch_bounds__(256)
void conv_gelu_kernel(const float* __restrict__ cw, const float* __restrict__ cb)
{
    int idx = blockIdx.x * 256 + threadIdx.x;     // < ROWS*DIN
    int c = idx & (DIN_ - 1);
    int l = (idx >> 9) & (L_ - 1);
    float w0 = cw[c * 3], w1 = cw[c * 3 + 1], w2 = cw[c * 3 + 2];
    float acc = fmaf(w1, g_u0[idx], cb[c]);
    if (l > 0)      acc = fmaf(w0, g_u0[idx - DIN_], acc);
    if (l < L_ - 1) acc = fmaf(w2, g_u0[idx + DIN_], acc);
    g_u[idx] = 0.5f * acc * (1.0f + erff(acc * 0.70710678118654752f));
}

// =================================================================
// Fused skinny projection + softplus/decay (dt cols 0..7)
// =================================================================
__global__ __launch_bounds__(256)
void dtproj_kernel(const float* __restrict__ Wx,
                   const float* __restrict__ dt_bias, const float* __restrict__ A_log)
{
    int row  = blockIdx.x * 8 + (threadIdx.x >> 5);
    int lane = threadIdx.x & 31;
    const float* ur = g_u + (size_t)row * DIN_;

    float acc[8];
    #pragma unroll
    for (int j = 0; j < 8; j++) acc[j] = 0.f;

    #pragma unroll 4
    for (int i = 0; i < 16; i++) {
        int k = i * 32 + lane;
        float uv = ur[k];
        const float* wr = Wx + (size_t)k * XPN;
        float4 wa = *(const float4*)(wr);
        float4 wb = *(const float4*)(wr + 4);
        acc[0] = fmaf(uv, wa.x, acc[0]); acc[1] = fmaf(uv, wa.y, acc[1]);
        acc[2] = fmaf(uv, wa.z, acc[2]); acc[3] = fmaf(uv, wa.w, acc[3]);
        acc[4] = fmaf(uv, wb.x, acc[4]); acc[5] = fmaf(uv, wb.y, acc[5]);
        acc[6] = fmaf(uv, wb.z, acc[6]); acc[7] = fmaf(uv, wb.w, acc[7]);
    }
    #pragma unroll
    for (int o = 16; o; o >>= 1)
        #pragma unroll
        for (int j = 0; j < 8; j++)
            acc[j] += __shfl_xor_sync(0xffffffffu, acc[j], o);

    if (lane < 8) {
        float v  = acc[lane] + dt_bias[lane];
        float dt = (v > 20.f) ? v : log1pf(expf(v));
        float dec = expf(dt * -expf(A_log[lane]));
        float* dd = g_dd + (size_t)row * (HSS * 2) + lane * 2;
        dd[0] = dt;
        dd[1] = dec;
    }
}

// =================================================================
// Sequential selective scan.  128 blocks = (b, h, p-half).
// 256 threads: thread owns (p_local = t>>3, 8 n values = (t&7)*8..+7).
// Depth-4 load pipeline + BATCHED reduction: the 4 steps' butterfly
// chains run interleaved (4 independent 3-SHFL chains) instead of
// serially, cutting reduction latency per 4-step group ~312->~78 cyc.
// =================================================================
struct SStep { float4 b0, b1, c0, c1; float xv, dt, dec; };

__device__ __forceinline__ SStep ld_step(const float* pB, const float* pC,
                                         const float* pX, const float* pD, int l)
{
    SStep S;
    const float* bq = pB + (size_t)l * XPN;
    const float* cq = pC + (size_t)l * XPN;
    S.b0 = *(const float4*)bq;       S.b1 = *(const float4*)(bq + 4);
    S.c0 = *(const float4*)cq;       S.c1 = *(const float4*)(cq + 4);
    S.xv = pX[(size_t)l * DIN_];
    float2 d = *(const float2*)(pD + (size_t)l * (HSS * 2));
    S.dt = d.x; S.dec = d.y;
    return S;
}

// FMA phase only: update hs, return this step's partial y (8-wide dot)
__device__ __forceinline__ float fma_step(const SStep& S, float* hs)
{
    float a = S.dt * S.xv;
    float yp;
    hs[0] = fmaf(hs[0], S.dec, a * S.b0.x); yp = hs[0] * S.c0.x;
    hs[1] = fmaf(hs[1], S.dec, a * S.b0.y); yp = fmaf(hs[1], S.c0.y, yp);
    hs[2] = fmaf(hs[2], S.dec, a * S.b0.z); yp = fmaf(hs[2], S.c0.z, yp);
    hs[3] = fmaf(hs[3], S.dec, a * S.b0.w); yp = fmaf(hs[3], S.c0.w, yp);
    hs[4] = fmaf(hs[4], S.dec, a * S.b1.x); yp = fmaf(hs[4], S.c1.x, yp);
    hs[5] = fmaf(hs[5], S.dec, a * S.b1.y); yp = fmaf(hs[5], S.c1.y, yp);
    hs[6] = fmaf(hs[6], S.dec, a * S.b1.z); yp = fmaf(hs[6], S.c1.z, yp);
    hs[7] = fmaf(hs[7], S.dec, a * S.b1.w); yp = fmaf(hs[7], S.c1.w, yp);
    return yp;
}

__global__ __launch_bounds__(256)
void scan_kernel()
{
    const int t   = threadIdx.x;
    const int blk = blockIdx.x;          // 0..127
    const int b   = blk >> 4;
    const int h   = (blk >> 1) & 7;
    const int s   = blk & 1;
    const int pl  = t >> 3;              // 0..31
    const int j   = t & 7;
    const int nb  = j << 3;
    const int p   = (s << 5) + pl;       // 0..63

    const float* pB = g_dbc + (size_t)b * L_ * XPN + HSS + nb;
    const float* pC = g_dbc + (size_t)b * L_ * XPN + HSS + NSS + nb;
    const float* pX = g_u   + (size_t)b * L_ * DIN_ + h * PSS + p;
    const float* pD = g_dd  + (size_t)b * L_ * (HSS * 2) + h * 2;
    float*       pY = g_ys  + (size_t)b * L_ * DIN_ + h * PSS + p;

    float hs[8];
    #pragma unroll
    for (int i = 0; i < 8; i++) hs[i] = 0.f;

    SStep sp0 = ld_step(pB, pC, pX, pD, 0);
    SStep sp1 = ld_step(pB, pC, pX, pD, 1);
    SStep sp2 = ld_step(pB, pC, pX, pD, 2);
    SStep sp3 = ld_step(pB, pC, pX, pD, 3);

    #pragma unroll 1
    for (int l = 0; l < L_; l += 4) {
        SStep n0 = {}, n1 = {}, n2 = {}, n3 = {};
        if (l + 4 < L_) {
            n0 = ld_step(pB, pC, pX, pD, l + 4);
            n1 = ld_step(pB, pC, pX, pD, l + 5);
            n2 = ld_step(pB, pC, pX, pD, l + 6);
            n3 = ld_step(pB, pC, pX, pD, l + 7);
        }
        // FMA phase (hs recurrence is a short serial FMA chain)
        float y0 = fma_step(sp0, hs);
        float y1 = fma_step(sp1, hs);
        float y2 = fma_step(sp2, hs);
        float y3 = fma_step(sp3, hs);
        // Batched butterfly: 4 independent chains interleaved
        y0 += __shfl_xor_sync(0xffffffffu, y0, 1);
        y1 += __shfl_xor_sync(0xffffffffu, y1, 1);
        y2 += __shfl_xor_sync(0xffffffffu, y2, 1);
        y3 += __shfl_xor_sync(0xffffffffu, y3, 1);
        y0 += __shfl_xor_sync(0xffffffffu, y0, 2);
        y1 += __shfl_xor_sync(0xffffffffu, y1, 2);
        y2 += __shfl_xor_sync(0xffffffffu, y2, 2);
        y3 += __shfl_xor_sync(0xffffffffu, y3, 2);
        y0 += __shfl_xor_sync(0xffffffffu, y0, 4);
        y1 += __shfl_xor_sync(0xffffffffu, y1, 4);
        y2 += __shfl_xor_sync(0xffffffffu, y2, 4);
        y3 += __shfl_xor_sync(0xffffffffu, y3, 4);
        if (j == 0) {
            pY[(size_t)(l + 0) * DIN_] = y0;
            pY[(size_t)(l + 1) * DIN_] = y1;
            pY[(size_t)(l + 2) * DIN_] = y2;
            pY[(size_t)(l + 3) * DIN_] = y3;
        }
        sp0 = n0; sp1 = n1; sp2 = n2; sp3 = n3;
    }
}

// =================================================================
// z = LN_512( ys + u * Ds[c>>6] ) : one warp per row
// =================================================================
__global__ __launch_bounds__(256)
void postln_kernel(const float* __restrict__ Ds,
                   const float* __restrict__ ow, const float* __restrict__ ob)
{
    int row  = blockIdx.x * 8 + (threadIdx.x >> 5);
    int lane = threadIdx.x & 31;
    const float* yr = g_ys + (size_t)row * DIN_ + lane * 16;
    const float* ur = g_u  + (size_t)row * DIN_ + lane * 16;
    float d = Ds[lane >> 2];
    float v[16];
    float s = 0.f, q = 0.f;
    #pragma unroll
    for (int k = 0; k < 4; k++) {
        float4 yv = *(const float4*)(yr + k * 4);
        float4 uv = *(const float4*)(ur + k * 4);
        float t0 = yv.x + uv.x * d, t1 = yv.y + uv.y * d;
        float t2 = yv.z + uv.z * d, t3 = yv.w + uv.w * d;
        v[k*4+0]=t0; v[k*4+1]=t1; v[k*4+2]=t2; v[k*4+3]=t3;
        s += t0 + t1 + t2 + t3;
        q = fmaf(t0,t0,q); q = fmaf(t1,t1,q); q = fmaf(t2,t2,q); q = fmaf(t3,t3,q);
    }
    #pragma unroll
    for (int o = 16; o; o >>= 1) {
        s += __shfl_xor_sync(0xffffffffu, s, o);
        q += __shfl_xor_sync(0xffffffffu, q, o);
    }
    float m  = s * (1.0f / DIN_);
    float rs = rsqrtf(q * (1.0f / DIN_) - m * m + 1e-5f);
    float* zr = g_z + (size_t)row * DIN_ + lane * 16;
    #pragma unroll
    for (int k = 0; k < 4; k++) {
        float4 wv = *(const float4*)(ow + lane * 16 + k * 4);
        float4 bv = *(const float4*)(ob + lane * 16 + k * 4);
        float4 o;
        o.x = (v[k*4+0] - m) * rs * wv.x + bv.x;
        o.y = (v[k*4+1] - m) * rs * wv.y + bv.y;
        o.z = (v[k*4+2] - m) * rs * wv.z + bv.z;
        o.w = (v[k*4+3] - m) * rs * wv.w + bv.w;
        *(float4*)(zr + k * 4) = o;
    }
}

// =================================================================
extern "C" void kernel_launch(void* const* d_in, const int* in_sizes, int n_in,
                              void* d_out, int out_size)
{
    const float* src     = (const float*)d_in[0];
    const float* ln_w    = (const float*)d_in[1];
    const float* ln_b    = (const float*)d_in[2];
    const float* W_in    = (const float*)d_in[3];
    const float* conv_w  = (const float*)d_in[4];
    const float* conv_b  = (const float*)d_in[5];
    const float* W_xproj = (const float*)d_in[6];
    const float* dt_bias = (const float*)d_in[7];
    const float* A_log   = (const float*)d_in[8];
    const float* Ds      = (const float*)d_in[9];
    const float* oln_w   = (const float*)d_in[10];
    const float* oln_b   = (const float*)d_in[11];
    const float* W_out   = (const float*)d_in[12];
    float* out = (float*)d_out;

    float *px, *pu0, *pu, *pdbc, *pz;
    cudaGetSymbolAddress((void**)&px,   g_x);
    cudaGetSymbolAddress((void**)&pu0,  g_u0);
    cudaGetSymbolAddress((void**)&pu,   g_u);
    cudaGetSymbolAddress((void**)&pdbc, g_dbc);
    cudaGetSymbolAddress((void**)&pz,   g_z);

    ln1_kernel<<<ROWS / 8, 256>>>(src, ln_w, ln_b);

    // GEMM1: u0 = x @ W_in   [16384x256] @ [256x512]
    dim3 g1(DIN_ / 128, ROWS / 128);                // 4 x 128
    gemm128_kernel<false><<<g1, 256>>>(px, W_in, pu0, nullptr, DIN_, D_);

    conv_gelu_kernel<<<(ROWS * DIN_) / 256, 256>>>(conv_w, conv_b);

    // GEMM2 (B||C cols 8..135, exact 128-wide): ld = 136 on both sides
    dim3 g2(1, ROWS / 128);                         // 1 x 128
    gemm128_kernel<false><<<g2, 256>>>(pu, W_xproj + HSS, pdbc + HSS, nullptr,
                                       XPN, DIN_);

    // dt cols 0..7 fused with softplus/decay
    dtproj_kernel<<<ROWS / 8, 256>>>(W_xproj, dt_bias, A_log);

    scan_kernel<<<B_ * HSS * 2, 256>>>();

    postln_kernel<<<ROWS / 8, 256>>>(Ds, oln_w, oln_b);

    // GEMM3: out = src + z @ W_out  [16384x512] @ [512x256]
    dim3 g3(D_ / 128, ROWS / 128);                  // 2 x 128
    gemm128_kernel<true><<<g3, 256>>>(pz, W_out, out, src, D_, DIN_);
}